// round 3
// baseline (speedup 1.0000x reference)
#include <cuda_runtime.h>
#include <cstdint>

#define BATCH 2
#define SEQN 4096
#define CDIM 256
#define NH 8
#define DH 32
#define TWOC 512
#define SCALE 25.0f

// Scratch (no cudaMalloc allowed): qkv projection + normalized q/k in [bh][n][d] layout
__device__ float g_qkv[BATCH * SEQN * TWOC];              // 16 MB
__device__ float g_q[BATCH * NH * SEQN * DH];             // 8 MB
__device__ float g_k[BATCH * NH * SEQN * DH];             // 8 MB

// ---------------------------------------------------------------------------
// Kernel 1: qkv = x @ W   (M=8192, N=512, K=256)  classic smem-tiled SGEMM
// BM=64, BN=64, BK=16, 256 threads, 4x4 microtile
// ---------------------------------------------------------------------------
__global__ __launch_bounds__(256) void qkv_gemm_kernel(
    const float* __restrict__ x, const float* __restrict__ w)
{
    __shared__ float As[64][17];
    __shared__ float Bs[16][65];

    const int tid = threadIdx.x;
    const int tx = tid & 15;         // 0..15 -> col group
    const int ty = tid >> 4;         // 0..15 -> row group
    const int rowBase = blockIdx.y * 64;
    const int colBase = blockIdx.x * 64;

    float acc[4][4];
#pragma unroll
    for (int i = 0; i < 4; i++)
#pragma unroll
        for (int j = 0; j < 4; j++) acc[i][j] = 0.f;

    for (int k0 = 0; k0 < CDIM; k0 += 16) {
        // load A tile 64x16 (float4 per thread)
        {
            const int r = tid >> 2;          // 0..63
            const int kk = (tid & 3) * 4;    // 0,4,8,12
            float4 a = *reinterpret_cast<const float4*>(
                x + (size_t)(rowBase + r) * CDIM + k0 + kk);
            As[r][kk + 0] = a.x; As[r][kk + 1] = a.y;
            As[r][kk + 2] = a.z; As[r][kk + 3] = a.w;
        }
        // load B tile 16x64 (float4 per thread)
        {
            const int r = tid >> 4;          // 0..15
            const int c = (tid & 15) * 4;    // 0..60
            float4 b = *reinterpret_cast<const float4*>(
                w + (size_t)(k0 + r) * TWOC + colBase + c);
            Bs[r][c + 0] = b.x; Bs[r][c + 1] = b.y;
            Bs[r][c + 2] = b.z; Bs[r][c + 3] = b.w;
        }
        __syncthreads();

#pragma unroll
        for (int kk = 0; kk < 16; kk++) {
            float ar[4], br[4];
#pragma unroll
            for (int i = 0; i < 4; i++) ar[i] = As[ty * 4 + i][kk];
#pragma unroll
            for (int j = 0; j < 4; j++) br[j] = Bs[kk][tx * 4 + j];
#pragma unroll
            for (int i = 0; i < 4; i++)
#pragma unroll
                for (int j = 0; j < 4; j++) acc[i][j] += ar[i] * br[j];
        }
        __syncthreads();
    }

#pragma unroll
    for (int i = 0; i < 4; i++) {
        float* orow = g_qkv + (size_t)(rowBase + ty * 4 + i) * TWOC + colBase + tx * 4;
#pragma unroll
        for (int j = 0; j < 4; j++) orow[j] = acc[i][j];
    }
}

// ---------------------------------------------------------------------------
// Kernel 1b: normalize 32-d vectors; one warp per (row, q/k, head) vector
// writes g_q / g_k in [b*H+h][n][d] layout
// ---------------------------------------------------------------------------
__global__ __launch_bounds__(256) void normalize_kernel()
{
    const int lane = threadIdx.x & 31;
    const int wid = blockIdx.x * 8 + (threadIdx.x >> 5);   // global warp id
    // wid in [0, 8192*16): row = wid/16, rem = wid%16, which = rem/8, h = rem%8
    const int row = wid >> 4;
    const int rem = wid & 15;
    const int which = rem >> 3;
    const int h = rem & 7;

    float v = g_qkv[(size_t)row * TWOC + which * CDIM + h * DH + lane];
    float ss = v * v;
#pragma unroll
    for (int o = 16; o > 0; o >>= 1) ss += __shfl_xor_sync(0xffffffffu, ss, o);
    float nv = v / (sqrtf(ss) + 1e-8f);

    const int b = row >> 12;          // row / 4096
    const int n = row & 4095;
    const size_t dst = ((size_t)(b * NH + h) * SEQN + n) * DH + lane;
    if (which == 0) g_q[dst] = nv; else g_k[dst] = nv;
}

// ---------------------------------------------------------------------------
// Kernel 2: scores + softmax, recompute style.
// CTA: 64 q-rows x full 4096 keys (16 tiles of 256). 256 threads.
// Thread microtile: 8 rows (warp-private) x 8 keys (interleaved lane+32*j).
// Pass A: row sums of exp(s-25) (warp shuffle reduce). Pass B: write exp/sum.
// (logits are bounded above by SCALE since q,k are unit vectors, so a fixed
//  shift of -SCALE replaces the row-max pass; exp(s-25) in [e^-50, 1].)
// ---------------------------------------------------------------------------
__global__ __launch_bounds__(256) void attn_softmax_kernel(float* __restrict__ out)
{
    const int bh = blockIdx.y;              // 0..15
    const int qBase = blockIdx.x * 64;
    const int rg = threadIdx.x >> 5;        // warp id = row group (8 rows)
    const int lane = threadIdx.x & 31;

    __shared__ float qS[64][33];
    __shared__ float kS[256][33];

    const float* qptr = g_q + ((size_t)bh * SEQN + qBase) * DH;
    const float* kbase = g_k + (size_t)bh * SEQN * DH;

    // load Q tile (coalesced; [r][d] matches global contiguity)
    for (int i = threadIdx.x; i < 64 * DH; i += 256)
        qS[i >> 5][i & 31] = qptr[i];

    float rowsum[8];
#pragma unroll
    for (int i = 0; i < 8; i++) rowsum[i] = 0.f;

    // ---------------- Pass A: row sums ----------------
    for (int kt = 0; kt < 16; kt++) {
        __syncthreads();
        const float* kp = kbase + (size_t)kt * 256 * DH;
#pragma unroll
        for (int i = threadIdx.x * 4; i < 256 * DH; i += 256 * 4) {
            float4 v = *reinterpret_cast<const float4*>(kp + i);
            const int key = i >> 5, d = i & 31;
            kS[key][d] = v.x; kS[key][d + 1] = v.y;
            kS[key][d + 2] = v.z; kS[key][d + 3] = v.w;
        }
        __syncthreads();

        float acc[8][8];
#pragma unroll
        for (int i = 0; i < 8; i++)
#pragma unroll
            for (int j = 0; j < 8; j++) acc[i][j] = 0.f;

#pragma unroll 8
        for (int dd = 0; dd < DH; dd++) {
            float qr[8], kr[8];
#pragma unroll
            for (int i = 0; i < 8; i++) qr[i] = qS[rg * 8 + i][dd];
#pragma unroll
            for (int j = 0; j < 8; j++) kr[j] = kS[lane + 32 * j][dd];
#pragma unroll
            for (int i = 0; i < 8; i++)
#pragma unroll
                for (int j = 0; j < 8; j++) acc[i][j] += qr[i] * kr[j];
        }
#pragma unroll
        for (int i = 0; i < 8; i++)
#pragma unroll
            for (int j = 0; j < 8; j++)
                rowsum[i] += __expf(acc[i][j] * SCALE - SCALE);
    }

    // warp-level reduce (each warp exclusively owns its 8 rows)
#pragma unroll
    for (int i = 0; i < 8; i++) {
#pragma unroll
        for (int o = 16; o > 0; o >>= 1)
            rowsum[i] += __shfl_xor_sync(0xffffffffu, rowsum[i], o);
        rowsum[i] = 1.f / rowsum[i];
    }

    // ---------------- Pass B: recompute + write ----------------
    float* obase = out + ((size_t)bh * SEQN + qBase) * SEQN;
    for (int kt = 0; kt < 16; kt++) {
        __syncthreads();
        const float* kp = kbase + (size_t)kt * 256 * DH;
#pragma unroll
        for (int i = threadIdx.x * 4; i < 256 * DH; i += 256 * 4) {
            float4 v = *reinterpret_cast<const float4*>(kp + i);
            const int key = i >> 5, d = i & 31;
            kS[key][d] = v.x; kS[key][d + 1] = v.y;
            kS[key][d + 2] = v.z; kS[key][d + 3] = v.w;
        }
        __syncthreads();

        float acc[8][8];
#pragma unroll
        for (int i = 0; i < 8; i++)
#pragma unroll
            for (int j = 0; j < 8; j++) acc[i][j] = 0.f;

#pragma unroll 8
        for (int dd = 0; dd < DH; dd++) {
            float qr[8], kr[8];
#pragma unroll
            for (int i = 0; i < 8; i++) qr[i] = qS[rg * 8 + i][dd];
#pragma unroll
            for (int j = 0; j < 8; j++) kr[j] = kS[lane + 32 * j][dd];
#pragma unroll
            for (int i = 0; i < 8; i++)
#pragma unroll
                for (int j = 0; j < 8; j++) acc[i][j] += qr[i] * kr[j];
        }
#pragma unroll
        for (int i = 0; i < 8; i++) {
            float* orow = obase + (size_t)(rg * 8 + i) * SEQN + kt * 256;
#pragma unroll
            for (int j = 0; j < 8; j++)
                orow[lane + 32 * j] = __expf(acc[i][j] * SCALE - SCALE) * rowsum[i];
        }
    }
}

// ---------------------------------------------------------------------------
extern "C" void kernel_launch(void* const* d_in, const int* in_sizes, int n_in,
                              void* d_out, int out_size)
{
    const float* x = (const float*)d_in[0];   // [2,4096,256]
    const float* w = (const float*)d_in[1];   // [256,512]
    float* out = (float*)d_out;               // [2,8,4096,4096]

    dim3 g1(TWOC / 64, (BATCH * SEQN) / 64);  // (8, 128)
    qkv_gemm_kernel<<<g1, 256>>>(x, w);

    // 8192 rows * 16 vectors = 131072 warps, 8 warps/CTA
    normalize_kernel<<<(BATCH * SEQN * 16) / 8, 256>>>();

    dim3 g2(SEQN / 64, BATCH * NH);           // (64, 16)
    attn_softmax_kernel<<<g2, 256>>>(out);
}